// round 14
// baseline (speedup 1.0000x reference)
#include <cuda_runtime.h>
#include <cstdint>

typedef unsigned long long ull;

#define F_DIM 16
#define N_DIM 8192
#define D_DIM 64
#define K_DIM 512
#define KQ    128               // codes per thread (quarter codebook)
#define DP    (D_DIM / 2)       // 32 d-pairs per row
#define KT    8                 // k per chunk
#define THREADS 256
#define TILE_M 128              // 64 row-pairs x 4 k-quarters = 256 threads
#define TILES_PER_F 64
#define GRIDB 148
#define EXTRA 136               // 136 blocks x 7 tiles + 12 x 6 = 1024 tiles
#define OUT_ELEMS ((size_t)F_DIM * N_DIM * D_DIM)   // 8388608

// ---- smem: 4 quarter regions [DP][KQ] float2 (-2*w), each staggered +16B so
// ---- the 4 per-phase addresses land on disjoint bank groups.
#define QSTRIDE (DP * KQ * 8 + 16)          // 32784; q*QSTRIDE % 128 = 16q
#define SM_NB   (4 * QSTRIDE)               // 131136
#define NSTRIDE (KQ * 8 + 16)               // 1040; offsets stay 16-staggered
#define SM_RED  (SM_NB + 4 * NSTRIDE)
#define SMEM_BYTES (SM_RED + THREADS * 4)   // ~136 KB

__device__ float g_partials[GRIDB];

// Packed fp32x2 FMA (Blackwell fma pipe: 2 fp32 MACs / instr, rt 2)
__device__ __forceinline__ ull ffma2(ull a, ull b, ull c) {
    ull d;
    asm("fma.rn.f32x2 %0, %1, %2, %3;" : "=l"(d) : "l"(a), "l"(b), "l"(c));
    return d;
}
__device__ __forceinline__ float2 u2f(ull v) {
    float2 r;
    asm("mov.b64 {%0, %1}, %2;" : "=f"(r.x), "=f"(r.y) : "l"(v));
    return r;
}

__global__ __launch_bounds__(THREADS, 1)
void vq_kernel(const float* __restrict__ x_all,
               const float* __restrict__ w_all,
               float* __restrict__ out) {
    extern __shared__ char smem[];
    float* red = (float*)(smem + SM_RED);

    const int tid = threadIdx.x;
    const int b   = blockIdx.x;
    const int q   = tid & 3;             // codebook quarter this thread scores
    const int pr  = tid >> 2;            // row-pair within tile (0..63)

    char* wbase = smem + q * QSTRIDE;                      // [DP][KQ] float2 = -2*w
    const float2* wn2 = (const float2*)(smem + SM_NB + q * NSTRIDE);  // (||w||^2, 0)

    // static contiguous tile schedule: 136 blocks x 7 tiles, 12 x 6
    const int ntile = (b < EXTRA) ? 7 : 6;
    const int t0    = (b < EXTRA) ? 7 * b : 6 * b + EXTRA;
    const int t1    = t0 + ntile;

    float loss_acc = 0.f;
    int cur_f = -1;
    const float* xg = nullptr;
    float* outf = nullptr;

    for (int t = t0; t < t1; ++t) {
        const int f = t >> 6;
        if (f != cur_f) {                                  // <=2 stagings per block
            __syncthreads();
            const float* wg = w_all + (size_t)f * D_DIM * K_DIM;
            // stage -2*w into the 4 quarter regions (coalesced over k)
            for (int i = tid; i < DP * K_DIM; i += THREADS) {
                int dp = i >> 9;
                int k  = i & (K_DIM - 1);
                int qq = k >> 7, j = k & (KQ - 1);
                float a = wg[(2 * dp) * K_DIM + k];
                float c = wg[(2 * dp + 1) * K_DIM + k];
                ((float2*)(smem + qq * QSTRIDE))[dp * KQ + j] =
                    make_float2(-2.f * a, -2.f * c);
            }
            __syncthreads();
            // norms: wn = 0.25 * sum((-2w)^2) (exact rescale)
            for (int k = tid; k < K_DIM; k += THREADS) {
                int qq = k >> 7, j = k & (KQ - 1);
                const float2* w2 = (const float2*)(smem + qq * QSTRIDE);
                float s = 0.f;
                #pragma unroll
                for (int dp = 0; dp < DP; ++dp) {
                    float2 v = w2[dp * KQ + j];
                    s = fmaf(v.x, v.x, s);
                    s = fmaf(v.y, v.y, s);
                }
                ((float2*)(smem + SM_NB + qq * NSTRIDE))[j] =
                    make_float2(0.25f * s, 0.f);
            }
            __syncthreads();
            cur_f = f;
            xg   = x_all + (size_t)f * N_DIM * D_DIM;
            outf = out + (size_t)f * N_DIM * D_DIM;
        }

        const int r0 = (t & (TILES_PER_F - 1)) * TILE_M + 2 * pr;
        const int r1 = r0 + 1;

        // both rows of the pair in registers as natural (d, d+1) pairs
        ull xa[DP], xb[DP];
        {
            const ulonglong2* pa = (const ulonglong2*)(xg + (size_t)r0 * D_DIM);
            const ulonglong2* pb = (const ulonglong2*)(xg + (size_t)r1 * D_DIM);
            #pragma unroll
            for (int j = 0; j < DP / 2; ++j) {
                ulonglong2 va = pa[j]; xa[2 * j] = va.x; xa[2 * j + 1] = va.y;
                ulonglong2 vb = pb[j]; xb[2 * j] = vb.x; xb[2 * j + 1] = vb.y;
            }
        }

        float bestA = 3.4e38f, bestB = 3.4e38f;
        int idxA = 0, idxB = 0;

        for (int k0 = 0; k0 < KQ; k0 += KT) {
            // acc init (||w||^2, 0); accumulate -2*x.w  (each wv feeds 4 ffma2)
            ull accA[KT], accB[KT];
            {
                const ulonglong2* ip = (const ulonglong2*)(wn2 + k0);
                #pragma unroll
                for (int j = 0; j < KT / 2; ++j) {
                    ulonglong2 v = ip[j];
                    accA[2 * j] = v.x; accA[2 * j + 1] = v.y;
                    accB[2 * j] = v.x; accB[2 * j + 1] = v.y;
                }
            }
            #pragma unroll
            for (int dp = 0; dp < DP; ++dp) {
                const ulonglong2* wp = (const ulonglong2*)(wbase + (dp * KQ + k0) * 8);
                ull xva = xa[dp], xvb = xb[dp];
                #pragma unroll
                for (int j = 0; j < KT / 2; ++j) {
                    ulonglong2 wv = wp[j];   // 4 distinct 16B addrs/warp, bank-disjoint
                    accA[2 * j]     = ffma2(xva, wv.x, accA[2 * j]);
                    accA[2 * j + 1] = ffma2(xva, wv.y, accA[2 * j + 1]);
                    accB[2 * j]     = ffma2(xvb, wv.x, accB[2 * j]);
                    accB[2 * j + 1] = ffma2(xvb, wv.y, accB[2 * j + 1]);
                }
            }
            // score = a.x + a.y ; first-min via strict <
            #pragma unroll
            for (int j = 0; j < KT; ++j) {
                float2 a = u2f(accA[j]);
                float sA = a.x + a.y;
                if (sA < bestA) { bestA = sA; idxA = k0 + j; }
                float2 c = u2f(accB[j]);
                float sB = c.x + c.y;
                if (sB < bestB) { bestB = sB; idxB = k0 + j; }
            }
        }

        // combine across the 4-lane quarter group; equal score -> lower k
        int kgA = q * KQ + idxA;
        int kgB = q * KQ + idxB;
        #pragma unroll
        for (int off = 1; off <= 2; off <<= 1) {
            float osA = __shfl_xor_sync(0xffffffffu, bestA, off);
            int   okA = __shfl_xor_sync(0xffffffffu, kgA, off);
            if (osA < bestA || (osA == bestA && okA < kgA)) { bestA = osA; kgA = okA; }
            float osB = __shfl_xor_sync(0xffffffffu, bestB, off);
            int   okB = __shfl_xor_sync(0xffffffffu, kgB, off);
            if (osB < bestB || (osB == bestB && okB < kgB)) { bestB = osB; kgB = okB; }
        }

        // each of the 4 threads writes one half-row of the pair
        {
            const int wrow  = (q >> 1) ? r1 : r0;
            const int whalf = q & 1;
            const int wk    = (q >> 1) ? kgB : kgA;
            const ull* xr   = (q >> 1) ? xb : xa;
            const float2* wr = (const float2*)(smem + (wk >> 7) * QSTRIDE);
            const int local = wk & (KQ - 1);
            float4* o4 = (float4*)(outf + (size_t)wrow * D_DIM + whalf * (D_DIM / 2));
            #pragma unroll
            for (int j = 0; j < 8; ++j) {
                int dp0 = whalf * 16 + 2 * j;
                float2 m0 = wr[dp0 * KQ + local];
                float2 m1 = wr[(dp0 + 1) * KQ + local];
                float q0x = -0.5f * m0.x, q0y = -0.5f * m0.y;   // undo -2w (exact)
                float q1x = -0.5f * m1.x, q1y = -0.5f * m1.y;
                float2 v0 = u2f(xr[dp0]), v1 = u2f(xr[dp0 + 1]);
                float d;
                d = q0x - v0.x; loss_acc = fmaf(d, d, loss_acc);
                d = q0y - v0.y; loss_acc = fmaf(d, d, loss_acc);
                d = q1x - v1.x; loss_acc = fmaf(d, d, loss_acc);
                d = q1y - v1.y; loss_acc = fmaf(d, d, loss_acc);
                o4[j] = make_float4(q0x, q0y, q1x, q1y);
            }
        }
    }

    // deterministic block reduction of loss partial
    __syncthreads();
    red[tid] = loss_acc;
    __syncthreads();
    #pragma unroll
    for (int s = THREADS / 2; s > 0; s >>= 1) {
        if (tid < s) red[tid] += red[tid + s];
        __syncthreads();
    }
    if (tid == 0) g_partials[b] = red[0];
}

__global__ void vq_finalize(float* out, int write_loss) {
    __shared__ float red[256];
    int t = threadIdx.x;
    red[t] = (t < GRIDB) ? g_partials[t] : 0.f;
    __syncthreads();
    #pragma unroll
    for (int s = 128; s > 0; s >>= 1) {
        if (t < s) red[t] += red[t + s];
        __syncthreads();
    }
    if (t == 0 && write_loss) {
        // loss = q_latent + 0.25 * e_latent = 1.25 * mean((q - x)^2)
        out[OUT_ELEMS] = 1.25f * red[0] / (float)OUT_ELEMS;
    }
}

extern "C" void kernel_launch(void* const* d_in, const int* in_sizes, int n_in,
                              void* d_out, int out_size) {
    const float* x = (const float*)d_in[0];
    const float* w = (const float*)d_in[1];
    float* out = (float*)d_out;

    cudaFuncSetAttribute(vq_kernel, cudaFuncAttributeMaxDynamicSharedMemorySize,
                         (int)SMEM_BYTES);
    vq_kernel<<<GRIDB, THREADS, SMEM_BYTES>>>(x, w, out);

    int write_loss = (out_size > (int)OUT_ELEMS) ? 1 : 0;
    vq_finalize<<<1, 256>>>(out, write_loss);
}

// round 15
// speedup vs baseline: 1.3565x; 1.3565x over previous
#include <cuda_runtime.h>
#include <cstdint>

typedef unsigned long long ull;

#define F_DIM 16
#define N_DIM 8192
#define D_DIM 64
#define K_DIM 512
#define DP    (D_DIM / 2)          // 32 d-pairs
#define KT    8                    // k per chunk (8 f32x2 accumulators per row)
#define THREADS 256
#define ROWS_PER_ITER (2 * THREADS)   // 512 rows per block-iteration (2 rows/thread)
#define ITERS 2                        // 1024 rows per block
#define BLOCKS_PER_F 8
#define NUM_BLOCKS (F_DIM * BLOCKS_PER_F)   // 128
#define OUT_ELEMS ((size_t)F_DIM * N_DIM * D_DIM)   // 8388608

#define SMEM_W_BYTES (DP * K_DIM * sizeof(float2))   // 131072 (holds -2*w)
#define SM_WN2 SMEM_W_BYTES                          // float2 (||w||^2, 0) per k
#define SM_RED (SM_WN2 + K_DIM * sizeof(float2))
#define SMEM_BYTES (SM_RED + THREADS * sizeof(float))

__device__ float g_partials[NUM_BLOCKS];
__device__ unsigned int g_done;     // zero-init; self-resetting (graph-replay safe)

// Packed fp32x2 FMA (Blackwell fma pipe: 2 fp32 MACs / instr, rt 2)
__device__ __forceinline__ ull ffma2(ull a, ull b, ull c) {
    ull d;
    asm("fma.rn.f32x2 %0, %1, %2, %3;" : "=l"(d) : "l"(a), "l"(b), "l"(c));
    return d;
}
__device__ __forceinline__ float2 u2f(ull v) {
    float2 r;
    asm("mov.b64 {%0, %1}, %2;" : "=f"(r.x), "=f"(r.y) : "l"(v));
    return r;
}

__global__ __launch_bounds__(THREADS, 1)
void vq_kernel(const float* __restrict__ x_all,
               const float* __restrict__ w_all,
               float* __restrict__ out, int write_loss) {
    extern __shared__ char smem[];
    float2* w2  = (float2*)smem;                    // [DP][K]: (-2w[2dp][k], -2w[2dp+1][k])
    float2* wn2 = (float2*)(smem + SM_WN2);         // [K]: (||w_k||^2, 0)
    float*  red = (float*)(smem + SM_RED);          // [THREADS]

    const int tid = threadIdx.x;
    const int f = blockIdx.x / BLOCKS_PER_F;
    const int rowbase = (blockIdx.x % BLOCKS_PER_F) * (N_DIM / BLOCKS_PER_F);

    const float* xg = x_all + (size_t)f * N_DIM * D_DIM;
    const float* wg = w_all + (size_t)f * D_DIM * K_DIM;
    float* outf = out + (size_t)f * N_DIM * D_DIM;

    // ---- stage -2*w repacked as d-pairs (exact scale) ----------------------
    for (int i = tid; i < DP * K_DIM; i += THREADS) {
        int dp = i >> 9;             // / K_DIM
        int k  = i & (K_DIM - 1);
        float a = wg[(2 * dp) * K_DIM + k];
        float b = wg[(2 * dp + 1) * K_DIM + k];
        w2[i] = make_float2(-2.f * a, -2.f * b);
    }
    __syncthreads();

    // ---- wn = ||w_k||^2 = 0.25 * sum((-2w)^2) (exact rescale) --------------
    for (int k = tid; k < K_DIM; k += THREADS) {
        float s = 0.f;
        #pragma unroll
        for (int dp = 0; dp < DP; ++dp) {
            float2 v = w2[dp * K_DIM + k];
            s = fmaf(v.x, v.x, s);
            s = fmaf(v.y, v.y, s);
        }
        wn2[k] = make_float2(0.25f * s, 0.f);
    }
    __syncthreads();

    float loss_acc = 0.f;

    for (int it = 0; it < ITERS; ++it) {
        const int r0 = rowbase + it * ROWS_PER_ITER + tid;
        const int r1 = r0 + THREADS;

        // x rows live in registers as natural (d, d+1) pairs
        ull xa[DP], xb[DP];
        {
            const ulonglong2* pa = (const ulonglong2*)(xg + (size_t)r0 * D_DIM);
            const ulonglong2* pb = (const ulonglong2*)(xg + (size_t)r1 * D_DIM);
            #pragma unroll
            for (int j = 0; j < DP / 2; ++j) {
                ulonglong2 va = pa[j]; xa[2 * j] = va.x; xa[2 * j + 1] = va.y;
                ulonglong2 vb = pb[j]; xb[2 * j] = vb.x; xb[2 * j + 1] = vb.y;
            }
        }

        float bestA = 3.4e38f, bestB = 3.4e38f;
        int idxA = 0, idxB = 0;

        for (int k0 = 0; k0 < K_DIM; k0 += KT) {
            // acc starts at (||w||^2, 0); ffma2 accumulates -2*x.w on top (fold)
            ull accA[KT], accB[KT];
            {
                const ulonglong2* ip = (const ulonglong2*)(wn2 + k0);
                #pragma unroll
                for (int j = 0; j < KT / 2; ++j) {
                    ulonglong2 v = ip[j];
                    accA[2 * j] = v.x; accA[2 * j + 1] = v.y;
                    accB[2 * j] = v.x; accB[2 * j + 1] = v.y;
                }
            }

            #pragma unroll
            for (int dp = 0; dp < DP; ++dp) {
                const ulonglong2* wp = (const ulonglong2*)(w2 + dp * K_DIM + k0);
                ull xva = xa[dp], xvb = xb[dp];
                #pragma unroll
                for (int j = 0; j < KT / 2; ++j) {
                    ulonglong2 wv = wp[j];  // broadcast LDS.128: 2 k's worth of d-pairs
                    accA[2 * j]     = ffma2(xva, wv.x, accA[2 * j]);
                    accA[2 * j + 1] = ffma2(xva, wv.y, accA[2 * j + 1]);
                    accB[2 * j]     = ffma2(xvb, wv.x, accB[2 * j]);
                    accB[2 * j + 1] = ffma2(xvb, wv.y, accB[2 * j + 1]);
                }
            }

            // score = ||w||^2 - 2*dot = a.x + a.y ; first-min via strict <
            #pragma unroll
            for (int j = 0; j < KT; ++j) {
                float2 a = u2f(accA[j]);
                float sA = a.x + a.y;
                if (sA < bestA) { bestA = sA; idxA = k0 + j; }
                float2 c = u2f(accB[j]);
                float sB = c.x + c.y;
                if (sB < bestB) { bestB = sB; idxB = k0 + j; }
            }
        }

        // ---- gather codes (w2 = -2w -> scale -0.5, exact), write + loss ----
        {
            float4* oA = (float4*)(outf + (size_t)r0 * D_DIM);
            float4* oB = (float4*)(outf + (size_t)r1 * D_DIM);
            #pragma unroll
            for (int j = 0; j < DP / 2; ++j) {
                float2 ma0 = w2[(2 * j) * K_DIM + idxA];
                float2 ma1 = w2[(2 * j + 1) * K_DIM + idxA];
                float qa0x = -0.5f * ma0.x, qa0y = -0.5f * ma0.y;
                float qa1x = -0.5f * ma1.x, qa1y = -0.5f * ma1.y;
                float2 va0 = u2f(xa[2 * j]), va1 = u2f(xa[2 * j + 1]);
                float d;
                d = qa0x - va0.x; loss_acc = fmaf(d, d, loss_acc);
                d = qa0y - va0.y; loss_acc = fmaf(d, d, loss_acc);
                d = qa1x - va1.x; loss_acc = fmaf(d, d, loss_acc);
                d = qa1y - va1.y; loss_acc = fmaf(d, d, loss_acc);
                oA[j] = make_float4(qa0x, qa0y, qa1x, qa1y);

                float2 mb0 = w2[(2 * j) * K_DIM + idxB];
                float2 mb1 = w2[(2 * j + 1) * K_DIM + idxB];
                float qb0x = -0.5f * mb0.x, qb0y = -0.5f * mb0.y;
                float qb1x = -0.5f * mb1.x, qb1y = -0.5f * mb1.y;
                float2 vb0 = u2f(xb[2 * j]), vb1 = u2f(xb[2 * j + 1]);
                d = qb0x - vb0.x; loss_acc = fmaf(d, d, loss_acc);
                d = qb0y - vb0.y; loss_acc = fmaf(d, d, loss_acc);
                d = qb1x - vb1.x; loss_acc = fmaf(d, d, loss_acc);
                d = qb1y - vb1.y; loss_acc = fmaf(d, d, loss_acc);
                oB[j] = make_float4(qb0x, qb0y, qb1x, qb1y);
            }
        }
    }

    // deterministic block reduction of loss partial
    __syncthreads();
    red[tid] = loss_acc;
    __syncthreads();
    #pragma unroll
    for (int s = THREADS / 2; s > 0; s >>= 1) {
        if (tid < s) red[tid] += red[tid + s];
        __syncthreads();
    }

    // ---- fused finalize: last block to arrive sums g_partials -------------
    __shared__ unsigned int s_last;
    if (tid == 0) {
        g_partials[blockIdx.x] = red[0];
        __threadfence();
        unsigned int prev = atomicAdd(&g_done, 1u);
        s_last = (prev == NUM_BLOCKS - 1) ? 1u : 0u;
    }
    __syncthreads();
    if (s_last) {
        // fixed-order tree over fixed indices -> deterministic
        float v = (tid < NUM_BLOCKS) ? g_partials[tid] : 0.f;
        red[tid] = v;
        __syncthreads();
        #pragma unroll
        for (int s = THREADS / 2; s > 0; s >>= 1) {
            if (tid < s) red[tid] += red[tid + s];
            __syncthreads();
        }
        if (tid == 0) {
            if (write_loss)
                out[OUT_ELEMS] = 1.25f * red[0] / (float)OUT_ELEMS;
            g_done = 0u;              // self-reset for next graph replay
        }
    }
}

extern "C" void kernel_launch(void* const* d_in, const int* in_sizes, int n_in,
                              void* d_out, int out_size) {
    const float* x = (const float*)d_in[0];
    const float* w = (const float*)d_in[1];
    float* out = (float*)d_out;

    cudaFuncSetAttribute(vq_kernel, cudaFuncAttributeMaxDynamicSharedMemorySize,
                         (int)SMEM_BYTES);
    int write_loss = (out_size > (int)OUT_ELEMS) ? 1 : 0;
    vq_kernel<<<NUM_BLOCKS, THREADS, SMEM_BYTES>>>(x, w, out, write_loss);
}